// round 6
// baseline (speedup 1.0000x reference)
#include <cuda_runtime.h>

#define MATOMS 8192
#define NGRAPH 16
#define NATOM  512
#define FDIM 128
#define HDIM 64
#define DDIM 16
#define SEIN 95
#define NLUT 1920         // 15 octaves (d^2 in [1,32768)) x 128 mantissa steps
#define SLICES 8
#define PSTRIDE 100       // per-atom partial stride: 5 shells x 20 (16B aligned)

__device__ float g_src[MATOMS * DDIM];
__device__ float g_shellp[SLICES * MATOMS * PSTRIDE];  // raw per-slice shell sums
__device__ float g_nodes[NLUT + 1];
__device__ float g_mu[NGRAPH * DDIM];
__device__ float g_part[256];
__device__ unsigned g_ctr;

__device__ __forceinline__ float wred(float v) {
#pragma unroll
    for (int o = 16; o; o >>= 1) v += __shfl_xor_sync(0xffffffffu, v, o);
    return v;
}
__device__ __forceinline__ float siluf(float z) { return z / (1.f + expf(-z)); }

#define FMA2(acc, a, b) \
    asm("fma.rn.f32x2 %0, %1, %2, %3;" : "=l"(acc) : "l"(a), "l"(b), "l"(acc))

__device__ __forceinline__ unsigned long long dup2(float a) {
    unsigned long long r;
    asm("mov.b64 %0, {%1, %1};" : "=l"(r) : "f"(a));
    return r;
}

// ---------------------------------------------------------------------------
// 1. Fused: blocks <256 -> per-atom source MLP; blocks >=256 -> LUT nodes on
//    the log-mantissa d^2 grid (exact gate-MLP eval per node).
// ---------------------------------------------------------------------------
__global__ void __launch_bounds__(256) src_lut_kernel(
    const float* __restrict__ x, const float* __restrict__ w1, const float* __restrict__ b1,
    const float* __restrict__ w2, const float* __restrict__ b2,
    const float* __restrict__ lng, const float* __restrict__ lnb,
    const float* __restrict__ slng, const float* __restrict__ slnb,
    const float* __restrict__ ks_p, const float* __restrict__ kw1,
    const float* __restrict__ kb1, const float* __restrict__ kw2,
    const float* __restrict__ kb2) {
    if (blockIdx.x >= 256) {
        int i = (blockIdx.x - 256) * 256 + threadIdx.x;
        if (i > NLUT) return;
        unsigned bits = (unsigned)(127 + (i >> 7)) << 23 | (unsigned)(i & 127) << 16;
        float t = __uint_as_float(bits);
        float dd = sqrtf(t);
        float screening = log1pf(expf(*ks_p));
        float base = expf(-screening * dd) / fmaxf(dd, 1e-6f);
        float gin[10];
        gin[0] = dd * (1.f / 5.f);
        gin[1] = dd * (1.f / 40.f);
#pragma unroll
        for (int r = 0; r < 8; r++) {
            float c = 5.f + 5.f * (float)r;
            float tt = dd - c;
            gin[2 + r] = expf(-tt * tt * (1.f / 25.f));
        }
        float out = kb2[0];
        for (int j = 0; j < 32; j++) {
            float z = kb1[j];
#pragma unroll
            for (int q = 0; q < 10; q++) z = fmaf(gin[q], kw1[q * 32 + j], z);
            out = fmaf(siluf(z), kw2[j], out);
        }
        g_nodes[i] = base * (1.f + tanhf(out));
        return;
    }
    __shared__ float sW1[FDIM * HDIM];
    __shared__ float sW2[HDIM * DDIM];
    __shared__ float sB1[HDIM], sB2[DDIM];
    __shared__ float sLnG[FDIM], sLnB[FDIM], sSLnG[DDIM], sSLnB[DDIM];
    __shared__ float xnB[8][FDIM];
    __shared__ float hB[8][HDIM];
    int tid = threadIdx.x;
    for (int i = tid; i < FDIM * HDIM; i += 256) sW1[i] = w1[i];
    for (int i = tid; i < HDIM * DDIM; i += 256) sW2[i] = w2[i];
    if (tid < HDIM) sB1[tid] = b1[tid];
    if (tid < DDIM) sB2[tid] = b2[tid];
    if (tid < FDIM) { sLnG[tid] = lng[tid]; sLnB[tid] = lnb[tid]; }
    if (tid < DDIM) { sSLnG[tid] = slng[tid]; sSLnB[tid] = slnb[tid]; }
    __syncthreads();
    int w = tid >> 5, lane = tid & 31;
    for (int t = 0; t < 4; t++) {
        int a = blockIdx.x * 32 + w * 4 + t;
        float4 v = ((const float4*)(x + a * FDIM))[lane];
        float s = wred(v.x + v.y + v.z + v.w);
        float m = s * (1.f / 128.f);
        float d0 = v.x - m, d1 = v.y - m, d2 = v.z - m, d3 = v.w - m;
        float ss = wred(d0 * d0 + d1 * d1 + d2 * d2 + d3 * d3);
        float rstd = rsqrtf(ss * (1.f / 128.f) + 1e-5f);
        int k0 = lane * 4;
        xnB[w][k0 + 0] = fmaf(d0 * rstd, sLnG[k0 + 0], sLnB[k0 + 0]);
        xnB[w][k0 + 1] = fmaf(d1 * rstd, sLnG[k0 + 1], sLnB[k0 + 1]);
        xnB[w][k0 + 2] = fmaf(d2 * rstd, sLnG[k0 + 2], sLnB[k0 + 2]);
        xnB[w][k0 + 3] = fmaf(d3 * rstd, sLnG[k0 + 3], sLnB[k0 + 3]);
        __syncwarp();
        float h0 = sB1[lane], h1 = sB1[lane + 32];
        for (int k = 0; k < FDIM; k++) {
            float xv = xnB[w][k];
            h0 = fmaf(xv, sW1[k * 64 + lane], h0);
            h1 = fmaf(xv, sW1[k * 64 + lane + 32], h1);
        }
        hB[w][lane] = siluf(h0);
        hB[w][lane + 32] = siluf(h1);
        __syncwarp();
        float oc = 0.f;
        if (lane < 16) {
            oc = sB2[lane];
            for (int k = 0; k < HDIM; k++) oc = fmaf(hB[w][k], sW2[k * 16 + lane], oc);
        }
        float s2 = oc;
#pragma unroll
        for (int o = 8; o; o >>= 1) s2 += __shfl_xor_sync(0xffffffffu, s2, o);
        float mm = s2 * (1.f / 16.f);
        float dv = oc - mm;
        float vs = dv * dv;
#pragma unroll
        for (int o = 8; o; o >>= 1) vs += __shfl_xor_sync(0xffffffffu, vs, o);
        float rs = rsqrtf(vs * (1.f / 16.f) + 1e-5f);
        if (lane < 16) g_src[a * DDIM + lane] = fmaf(dv * rs, sSLnG[lane], sSLnB[lane]);
        __syncwarp();
    }
}

// ---------------------------------------------------------------------------
// 2. Pairwise shells, THREAD-PER-ATOM, j uniform per warp (broadcast loads),
//    j split into 8 slices. No cross-lane reduction tail.
// ---------------------------------------------------------------------------
#define PAIR_SMEM_FLOATS (2048 + NATOM * 16 + 2 * NLUT + 128 + 16)
#define PAIR_SMEM (PAIR_SMEM_FLOATS * 4)

__global__ void __launch_bounds__(128, 4) pair_kernel(const float* __restrict__ pos) {
    extern __shared__ float psm[];
    float4* sP = (float4*)psm;                              // 512 float4
    float* sS = psm + 2048;                                 // [512][16]
    float2* sLutB = (float2*)(psm + 2048 + NATOM * 16);     // NLUT float2
    float* sPart = psm + 2048 + NATOM * 16 + 2 * NLUT;      // 128
    float* sMu = sPart + 128;                               // 16
    int tid = threadIdx.x;
    int b = blockIdx.x;
    int g = b >> 5;
    int tile = (b >> 1) & 15;
    int sg = b & 1;
    const float* pg = pos + g * NATOM * 3;
    for (int j = tid; j < NATOM; j += 128)
        sP[j] = make_float4(pg[j * 3 + 0], pg[j * 3 + 1], pg[j * 3 + 2], 0.f);
    const float* sgp = g_src + g * NATOM * DDIM;
    for (int idx = tid; idx < NATOM * 4; idx += 128) {
        int j = idx >> 2, c4 = idx & 3;
        ((float4*)(sS + j * 16))[c4] = ((const float4*)(sgp + j * 16))[c4];
    }
    for (int i = tid; i < NLUT; i += 128) {
        float a = g_nodes[i], bb = g_nodes[i + 1];
        sLutB[i] = make_float2(a, (bb - a) * (1.f / 65536.f));
    }
    __syncthreads();
    // per-graph mean subtract (identical FP order in every block -> deterministic)
    {
        int c = tid & 15, p = tid >> 4;  // p in 0..7
        float s = 0.f;
        for (int j = p; j < NATOM; j += 8) s += sS[j * 16 + c];
        sPart[tid] = s;
        __syncthreads();
        if (tid < 16) {
            float t = 0.f;
            for (int q = 0; q < 8; q++) t += sPart[q * 16 + tid];
            float mu = t * (1.f / (float)NATOM);
            sMu[tid] = mu;
            if (tile == 0 && sg == 0) g_mu[g * 16 + tid] = mu;
        }
        __syncthreads();
        for (int j = p; j < NATOM; j += 8) sS[j * 16 + c] -= sMu[c];
        __syncthreads();
    }
    int w = tid >> 5, lane = tid & 31;
    int s = sg * 4 + w;                 // j-slice 0..7
    int il = tile * 32 + lane;          // this thread's atom
    float4 pi = sP[il];
    unsigned long long accM[5][8];
    float accC[5], accR[5], accR2[5];
#pragma unroll
    for (int q = 0; q < 5; q++) {
        accC[q] = 0.f; accR[q] = 0.f; accR2[q] = 0.f;
#pragma unroll
        for (int p = 0; p < 8; p++) accM[q][p] = 0ull;
    }
    int j0 = s * 64;
#pragma unroll 2
    for (int jj = 0; jj < 64; jj++) {
        int j = j0 + jj;                 // uniform across warp -> broadcast loads
        float4 pj = sP[j];
        float dx = pi.x - pj.x, dy = pi.y - pj.y, dz = pi.z - pj.z;
        float d2 = fmaf(dx, dx, fmaf(dy, dy, fmaf(dz, dz, 1e-12f)));
        unsigned u = __float_as_uint(d2);
        int k = (int)(u >> 16) - 16256;
        k = min(max(k, 0), NLUT - 1);
        float fr = (float)(int)(u & 0xFFFFu);
        float2 L = sLutB[k];
        float ker = fmaf(L.y, fr, L.x);
        float d = sqrtf(d2);
        float m0 = (d2 >= 25.f && d2 < 100.f) ? 1.f : 0.f;
        float m1 = (d2 >= 100.f && d2 < 400.f) ? 1.f : 0.f;
        float m2 = (d2 >= 400.f && d2 < 1600.f) ? 1.f : 0.f;
        float m3 = (d2 >= 1600.f && d2 < 6400.f) ? 1.f : 0.f;
        float m4 = (d2 >= 6400.f) ? 1.f : 0.f;
        accC[0] += m0; accR[0] = fmaf(m0, d, accR[0]); accR2[0] = fmaf(m0, d2, accR2[0]);
        accC[1] += m1; accR[1] = fmaf(m1, d, accR[1]); accR2[1] = fmaf(m1, d2, accR2[1]);
        accC[2] += m2; accR[2] = fmaf(m2, d, accR[2]); accR2[2] = fmaf(m2, d2, accR2[2]);
        accC[3] += m3; accR[3] = fmaf(m3, d, accR[3]); accR2[3] = fmaf(m3, d2, accR2[3]);
        accC[4] += m4; accR[4] = fmaf(m4, d, accR[4]); accR2[4] = fmaf(m4, d2, accR2[4]);
        const ulonglong2* rp = (const ulonglong2*)(sS + j * 16);
        ulonglong2 u0 = rp[0], u1 = rp[1], u2 = rp[2], u3 = rp[3];
        unsigned long long W;
#define ACCQ(Q, MQ) { W = dup2(MQ * ker); \
        FMA2(accM[Q][0], W, u0.x); FMA2(accM[Q][1], W, u0.y); \
        FMA2(accM[Q][2], W, u1.x); FMA2(accM[Q][3], W, u1.y); \
        FMA2(accM[Q][4], W, u2.x); FMA2(accM[Q][5], W, u2.y); \
        FMA2(accM[Q][6], W, u3.x); FMA2(accM[Q][7], W, u3.y); }
        ACCQ(0, m0) ACCQ(1, m1) ACCQ(2, m2) ACCQ(3, m3) ACCQ(4, m4)
#undef ACCQ
    }
    // direct store: 25 x STG.128 per thread, coalescing via 16B sectors
    float* outp = g_shellp + ((s * MATOMS) + (g * NATOM + il)) * PSTRIDE;
#pragma unroll
    for (int q = 0; q < 5; q++) {
        ulonglong2* mp = (ulonglong2*)(outp + q * 20);
        ulonglong2 a;
        a.x = accM[q][0]; a.y = accM[q][1]; mp[0] = a;
        a.x = accM[q][2]; a.y = accM[q][3]; mp[1] = a;
        a.x = accM[q][4]; a.y = accM[q][5]; mp[2] = a;
        a.x = accM[q][6]; a.y = accM[q][7]; mp[3] = a;
        *(float4*)(outp + q * 20 + 16) = make_float4(accC[q], accR[q], accR2[q], 0.f);
    }
}

// ---------------------------------------------------------------------------
// 3. Head: merge 8 slices, finalize, LNs + MLPs, per-block partial energy;
//    last block (atomic counter) reduces 256 partials -> 16 graph energies.
// ---------------------------------------------------------------------------
#define HEAD_SMEM_FLOATS (6080 + 64 + 1024 + 16 + 10176 + 64 + 64 + 16 + 96 + 96 + 160 + 160 + 1280 + 512 + 16)
#define HEAD_SMEM (HEAD_SMEM_FLOATS * 4)

__device__ __forceinline__ float fin_shell(float v, int o, float i0, float i1, float i2,
                                           float i3, float i4) {
    int q = o / 19;
    int k = o - q * 19;
    float dv = (q == 0) ? i0 : (q == 1) ? i1 : (q == 2) ? i2 : (q == 3) ? i3 : i4;
    if (k == 16) return v;
    if (k == 18) return sqrtf(fmaf(v, dv, 1e-12f));
    return v * dv;
}

__global__ void __launch_bounds__(256) head_kernel(
    const float* __restrict__ seLnG_, const float* __restrict__ seLnB_,
    const float* __restrict__ seW1_, const float* __restrict__ seB1_,
    const float* __restrict__ seW2_, const float* __restrict__ seB2_,
    const float* __restrict__ ehLnG_, const float* __restrict__ ehLnB_,
    const float* __restrict__ ehW1_, const float* __restrict__ ehB1_,
    const float* __restrict__ ehW2_, const float* __restrict__ ehB2_,
    const float* __restrict__ far_gate, const float* __restrict__ energy_scale,
    float* __restrict__ out) {
    extern __shared__ float sm[];
    __shared__ unsigned sDone;
    float* seW1 = sm;
    float* seB1 = seW1 + 6080;
    float* seW2 = seB1 + 64;
    float* seB2 = seW2 + 1024;
    float* ehW1 = seB2 + 16;
    float* ehB1 = ehW1 + 10176;
    float* ehW2 = ehB1 + 64;
    float* ehB2s = ehW2 + 64;
    float* seLnG = ehB2s + 16;
    float* seLnB = seLnG + 96;
    float* ehLnG = seLnB + 96;
    float* ehLnB = ehLnG + 160;
    float* zALL = ehLnB + 160;
    float* hALL = zALL + 1280;
    float* sWsum = hALL + 512;
    int tid = threadIdx.x;
    for (int i = tid; i < 6080; i += 256) seW1[i] = seW1_[i];
    for (int i = tid; i < 1024; i += 256) seW2[i] = seW2_[i];
    for (int i = tid; i < 10176; i += 256) ehW1[i] = ehW1_[i];
    if (tid < 64) { seB1[tid] = seB1_[tid]; ehB1[tid] = ehB1_[tid]; ehW2[tid] = ehW2_[tid]; }
    if (tid < 16) seB2[tid] = seB2_[tid];
    if (tid == 0) ehB2s[0] = ehB2_[0];
    if (tid < 95) { seLnG[tid] = seLnG_[tid]; seLnB[tid] = seLnB_[tid]; }
    if (tid < 159) { ehLnG[tid] = ehLnG_[tid]; ehLnB[tid] = ehLnB_[tid]; }
    __syncthreads();
    int w = tid >> 5, lane = tid & 31;
    float* z = zALL + w * 160;
    float* h = hALL + w * 64;
    float scale = tanhf(*far_gate) * expf(*energy_scale);
    // index remap o (0..94) -> q*20 + k in the partial layout
    int o1 = lane + 32, o2 = lane + 64;
    int ix0 = (lane / 19) * 20 + (lane % 19);
    int ix1 = (o1 / 19) * 20 + (o1 % 19);
    int ix2 = (lane < 31) ? ((o2 / 19) * 20 + (o2 % 19)) : 0;
    float wsum = 0.f;
    for (int t = 0; t < 4; t++) {
        int a = blockIdx.x * 32 + w * 4 + t;
        int g = a >> 9;
        float v0 = 0.f, v1 = 0.f, v2 = 0.f;
        const float* pp = g_shellp + a * PSTRIDE;
#pragma unroll
        for (int sl = 0; sl < SLICES; sl++) {
            v0 += pp[ix0];
            v1 += pp[ix1];
            v2 += pp[ix2];
            pp += MATOMS * PSTRIDE;
        }
        if (lane == 31) v2 = 0.f;
        // counts at o = 16,35,54,73,92
        float C0 = __shfl_sync(0xffffffffu, v0, 16);
        float C1 = __shfl_sync(0xffffffffu, v1, 3);
        float C2 = __shfl_sync(0xffffffffu, v1, 22);
        float C3 = __shfl_sync(0xffffffffu, v2, 9);
        float C4 = __shfl_sync(0xffffffffu, v2, 28);
        float i0 = 1.f / fmaxf(C0, 1.f), i1 = 1.f / fmaxf(C1, 1.f);
        float i2 = 1.f / fmaxf(C2, 1.f), i3 = 1.f / fmaxf(C3, 1.f);
        float i4 = 1.f / fmaxf(C4, 1.f);
        v0 = fin_shell(v0, lane, i0, i1, i2, i3, i4);
        v1 = fin_shell(v1, lane + 32, i0, i1, i2, i3, i4);
        v2 = (lane < 31) ? fin_shell(v2, lane + 64, i0, i1, i2, i3, i4) : 0.f;
        // LN over 95
        float s = wred(v0 + v1 + v2);
        float m = s * (1.f / 95.f);
        float e0 = v0 - m, e1 = v1 - m, e2 = (lane < 31) ? (v2 - m) : 0.f;
        float ss = wred(e0 * e0 + e1 * e1 + e2 * e2);
        float rstd = rsqrtf(ss * (1.f / 95.f) + 1e-5f);
        z[lane] = fmaf(e0 * rstd, seLnG[lane], seLnB[lane]);
        z[lane + 32] = fmaf(e1 * rstd, seLnG[lane + 32], seLnB[lane + 32]);
        if (lane < 31) z[lane + 64] = fmaf(e2 * rstd, seLnG[lane + 64], seLnB[lane + 64]);
        __syncwarp();
        float h0 = seB1[lane], h1 = seB1[lane + 32];
        for (int k = 0; k < 95; k++) {
            float zv = z[k];
            h0 = fmaf(zv, seW1[k * 64 + lane], h0);
            h1 = fmaf(zv, seW1[k * 64 + lane + 32], h1);
        }
        h[lane] = siluf(h0);
        h[lane + 32] = siluf(h1);
        __syncwarp();
        float srcc = 0.f, embc = 0.f;
        if (lane < 16) {
            embc = seB2[lane];
            for (int k = 0; k < 64; k++) embc = fmaf(h[k], seW2[k * 16 + lane], embc);
            srcc = g_src[a * DDIM + lane] - g_mu[g * 16 + lane];
        }
        __syncwarp();
        if (lane < 16) {
            z[lane] = srcc;
            z[16 + lane] = embc;
            z[32 + lane] = srcc * embc;
            z[48 + lane] = srcc - embc;
        }
        z[64 + lane] = v0;
        z[96 + lane] = v1;
        if (lane < 31) z[128 + lane] = v2;
        __syncwarp();
        float a0 = z[lane], a1 = z[lane + 32], a2 = z[lane + 64], a3 = z[lane + 96];
        float a4 = (lane < 31) ? z[lane + 128] : 0.f;
        float s2 = wred(a0 + a1 + a2 + a3 + a4);
        float m2 = s2 * (1.f / 159.f);
        float q0 = a0 - m2, q1 = a1 - m2, q2 = a2 - m2, q3 = a3 - m2;
        float q4 = (lane < 31) ? (a4 - m2) : 0.f;
        float ss2 = wred(q0 * q0 + q1 * q1 + q2 * q2 + q3 * q3 + q4 * q4);
        float rstd2 = rsqrtf(ss2 * (1.f / 159.f) + 1e-5f);
        z[lane] = fmaf(q0 * rstd2, ehLnG[lane], ehLnB[lane]);
        z[lane + 32] = fmaf(q1 * rstd2, ehLnG[lane + 32], ehLnB[lane + 32]);
        z[lane + 64] = fmaf(q2 * rstd2, ehLnG[lane + 64], ehLnB[lane + 64]);
        z[lane + 96] = fmaf(q3 * rstd2, ehLnG[lane + 96], ehLnB[lane + 96]);
        if (lane < 31) z[lane + 128] = fmaf(q4 * rstd2, ehLnG[lane + 128], ehLnB[lane + 128]);
        __syncwarp();
        float g0 = ehB1[lane], g1 = ehB1[lane + 32];
        for (int k = 0; k < 159; k++) {
            float zv = z[k];
            g0 = fmaf(zv, ehW1[k * 64 + lane], g0);
            g1 = fmaf(zv, ehW1[k * 64 + lane + 32], g1);
        }
        g0 = siluf(g0);
        g1 = siluf(g1);
        float p = wred(g0 * ehW2[lane] + g1 * ehW2[lane + 32]);
        if (lane == 0) wsum += (p + ehB2s[0]) * scale;
        __syncwarp();
    }
    if (lane == 0) sWsum[w] = wsum;
    __syncthreads();
    if (tid == 0) {
        float ssum = 0.f;
#pragma unroll
        for (int q = 0; q < 8; q++) ssum += sWsum[q];
        g_part[blockIdx.x] = ssum;
        __threadfence();
        unsigned o = atomicAdd(&g_ctr, 1u);
        sDone = (o == 255u) ? 1u : 0u;
    }
    __syncthreads();
    if (sDone) {
        float v = g_part[tid];
        v += __shfl_xor_sync(0xffffffffu, v, 1);
        v += __shfl_xor_sync(0xffffffffu, v, 2);
        v += __shfl_xor_sync(0xffffffffu, v, 4);
        v += __shfl_xor_sync(0xffffffffu, v, 8);
        if ((tid & 15) == 0) out[tid >> 4] = v;
        if (tid == 0) g_ctr = 0u;
    }
}

extern "C" void kernel_launch(void* const* d_in, const int* in_sizes, int n_in,
                              void* d_out, int out_size) {
    const float* x = (const float*)d_in[0];
    const float* pos = (const float*)d_in[1];
    const float* in_ln_g = (const float*)d_in[4];
    const float* in_ln_b = (const float*)d_in[5];
    const float* src_w1 = (const float*)d_in[6];
    const float* src_b1 = (const float*)d_in[7];
    const float* src_w2 = (const float*)d_in[8];
    const float* src_b2 = (const float*)d_in[9];
    const float* src_ln_g = (const float*)d_in[10];
    const float* src_ln_b = (const float*)d_in[11];
    const float* se_ln_g = (const float*)d_in[12];
    const float* se_ln_b = (const float*)d_in[13];
    const float* se_w1 = (const float*)d_in[14];
    const float* se_b1 = (const float*)d_in[15];
    const float* se_w2 = (const float*)d_in[16];
    const float* se_b2 = (const float*)d_in[17];
    const float* eh_ln_g = (const float*)d_in[18];
    const float* eh_ln_b = (const float*)d_in[19];
    const float* eh_w1 = (const float*)d_in[20];
    const float* eh_b1 = (const float*)d_in[21];
    const float* eh_w2 = (const float*)d_in[22];
    const float* eh_b2 = (const float*)d_in[23];
    const float* k_screen = (const float*)d_in[24];
    const float* kg_w1 = (const float*)d_in[25];
    const float* kg_b1 = (const float*)d_in[26];
    const float* kg_w2 = (const float*)d_in[27];
    const float* kg_b2 = (const float*)d_in[28];
    const float* far_gate = (const float*)d_in[29];
    const float* energy_scale = (const float*)d_in[30];
    float* out = (float*)d_out;

    cudaFuncSetAttribute(pair_kernel, cudaFuncAttributeMaxDynamicSharedMemorySize, PAIR_SMEM);
    cudaFuncSetAttribute(head_kernel, cudaFuncAttributeMaxDynamicSharedMemorySize, HEAD_SMEM);

    src_lut_kernel<<<256 + (NLUT + 1 + 255) / 256, 256>>>(
        x, src_w1, src_b1, src_w2, src_b2, in_ln_g, in_ln_b, src_ln_g, src_ln_b,
        k_screen, kg_w1, kg_b1, kg_w2, kg_b2);
    pair_kernel<<<NGRAPH * 32, 128, PAIR_SMEM>>>(pos);
    head_kernel<<<MATOMS / 32, 256, HEAD_SMEM>>>(se_ln_g, se_ln_b, se_w1, se_b1, se_w2, se_b2,
                                                 eh_ln_g, eh_ln_b, eh_w1, eh_b1, eh_w2, eh_b2,
                                                 far_gate, energy_scale, out);
}

// round 7
// speedup vs baseline: 1.2834x; 1.2834x over previous
#include <cuda_runtime.h>

#define MATOMS 8192
#define NGRAPH 16
#define NATOM  512
#define FDIM 128
#define HDIM 64
#define DDIM 16
#define SEIN 95
#define NLUT 1920         // 15 octaves (d^2 in [1,32768)) x 128 mantissa steps

__device__ float g_src[MATOMS * DDIM];
__device__ float g_shell[MATOMS * SEIN];   // RAW per-shell sums (finalized in head)
__device__ float g_nodes[NLUT + 1];
__device__ float g_mu[NGRAPH * DDIM];
__device__ float g_part[256];
__device__ unsigned g_ctr;

__device__ __forceinline__ float wred(float v) {
#pragma unroll
    for (int o = 16; o; o >>= 1) v += __shfl_xor_sync(0xffffffffu, v, o);
    return v;
}
__device__ __forceinline__ float siluf(float z) { return z / (1.f + expf(-z)); }

#define FMA2(acc, a, b) \
    asm("fma.rn.f32x2 %0, %1, %2, %3;" : "=l"(acc) : "l"(a), "l"(b), "l"(acc))

__device__ __forceinline__ unsigned long long dup2(float a) {
    unsigned long long r;
    asm("mov.b64 %0, {%1, %1};" : "=l"(r) : "f"(a));
    return r;
}
__device__ __forceinline__ unsigned long long pack2(float a, float b) {
    unsigned long long r;
    asm("mov.b64 %0, {%1, %2};" : "=l"(r) : "f"(a), "f"(b));
    return r;
}
__device__ __forceinline__ void unpk(unsigned long long v, float& a, float& b) {
    asm("mov.b64 {%0, %1}, %2;" : "=f"(a), "=f"(b) : "l"(v));
}

// ---------------------------------------------------------------------------
// 1. Fused: blocks <256 -> per-atom source MLP (4 atoms concurrent, f32x2);
//    blocks >=256 -> LUT nodes, gate weights staged in smem.
// ---------------------------------------------------------------------------
__global__ void __launch_bounds__(256) src_lut_kernel(
    const float* __restrict__ x, const float* __restrict__ w1, const float* __restrict__ b1,
    const float* __restrict__ w2, const float* __restrict__ b2,
    const float* __restrict__ lng, const float* __restrict__ lnb,
    const float* __restrict__ slng, const float* __restrict__ slnb,
    const float* __restrict__ ks_p, const float* __restrict__ kw1,
    const float* __restrict__ kb1, const float* __restrict__ kw2,
    const float* __restrict__ kb2) {
    __shared__ float sW1[FDIM * HDIM];      // reused by LUT branch
    __shared__ float sW2[HDIM * DDIM];
    __shared__ float sB1[HDIM], sB2[DDIM];
    __shared__ float sLnG[FDIM], sLnB[FDIM], sSLnG[DDIM], sSLnB[DDIM];
    __shared__ float xnB[8][4][FDIM];
    __shared__ float hB[8][4][HDIM];
    int tid = threadIdx.x;
    if (blockIdx.x >= 256) {
        float* kw1s = sW1;              // 320
        float* kb1s = sW1 + 320;        // 32
        float* kw2s = sW1 + 352;        // 32
        for (int i = tid; i < 320; i += 256) kw1s[i] = kw1[i];
        if (tid < 32) { kb1s[tid] = kb1[tid]; kw2s[tid] = kw2[tid]; }
        __syncthreads();
        int i = (blockIdx.x - 256) * 256 + tid;
        if (i > NLUT) return;
        unsigned bits = (unsigned)(127 + (i >> 7)) << 23 | (unsigned)(i & 127) << 16;
        float t = __uint_as_float(bits);
        float dd = sqrtf(t);
        float screening = log1pf(expf(*ks_p));
        float base = expf(-screening * dd) / fmaxf(dd, 1e-6f);
        float gin[10];
        gin[0] = dd * (1.f / 5.f);
        gin[1] = dd * (1.f / 40.f);
#pragma unroll
        for (int r = 0; r < 8; r++) {
            float c = 5.f + 5.f * (float)r;
            float tt = dd - c;
            gin[2 + r] = expf(-tt * tt * (1.f / 25.f));
        }
        float out = kb2[0];
#pragma unroll 4
        for (int j = 0; j < 32; j++) {
            float z = kb1s[j];
#pragma unroll
            for (int q = 0; q < 10; q++) z = fmaf(gin[q], kw1s[q * 32 + j], z);
            out = fmaf(siluf(z), kw2s[j], out);
        }
        g_nodes[i] = base * (1.f + tanhf(out));
        return;
    }
    for (int i = tid; i < FDIM * HDIM; i += 256) sW1[i] = w1[i];
    for (int i = tid; i < HDIM * DDIM; i += 256) sW2[i] = w2[i];
    if (tid < HDIM) sB1[tid] = b1[tid];
    if (tid < DDIM) sB2[tid] = b2[tid];
    if (tid < FDIM) { sLnG[tid] = lng[tid]; sLnB[tid] = lnb[tid]; }
    if (tid < DDIM) { sSLnG[tid] = slng[tid]; sSLnB[tid] = slnb[tid]; }
    __syncthreads();
    int w = tid >> 5, lane = tid & 31;
    int aBase = blockIdx.x * 32 + w * 4;
    // LN(x) for 4 atoms -> xnB
#pragma unroll
    for (int t = 0; t < 4; t++) {
        float4 v = ((const float4*)(x + (aBase + t) * FDIM))[lane];
        float s = wred(v.x + v.y + v.z + v.w);
        float m = s * (1.f / 128.f);
        float d0 = v.x - m, d1 = v.y - m, d2 = v.z - m, d3 = v.w - m;
        float ss = wred(d0 * d0 + d1 * d1 + d2 * d2 + d3 * d3);
        float rstd = rsqrtf(ss * (1.f / 128.f) + 1e-5f);
        int k0 = lane * 4;
        xnB[w][t][k0 + 0] = fmaf(d0 * rstd, sLnG[k0 + 0], sLnB[k0 + 0]);
        xnB[w][t][k0 + 1] = fmaf(d1 * rstd, sLnG[k0 + 1], sLnB[k0 + 1]);
        xnB[w][t][k0 + 2] = fmaf(d2 * rstd, sLnG[k0 + 2], sLnB[k0 + 2]);
        xnB[w][t][k0 + 3] = fmaf(d3 * rstd, sLnG[k0 + 3], sLnB[k0 + 3]);
    }
    __syncwarp();
    // fc1: lane owns channels 2l, 2l+1; 4 atoms concurrent; f32x2
    unsigned long long hAcc0, hAcc1, hAcc2, hAcc3;
    {
        float2 bb = ((const float2*)sB1)[lane];
        unsigned long long binit = pack2(bb.x, bb.y);
        hAcc0 = binit; hAcc1 = binit; hAcc2 = binit; hAcc3 = binit;
    }
#pragma unroll 4
    for (int k = 0; k < FDIM; k++) {
        unsigned long long wp = *(const unsigned long long*)(sW1 + k * 64 + lane * 2);
        FMA2(hAcc0, dup2(xnB[w][0][k]), wp);
        FMA2(hAcc1, dup2(xnB[w][1][k]), wp);
        FMA2(hAcc2, dup2(xnB[w][2][k]), wp);
        FMA2(hAcc3, dup2(xnB[w][3][k]), wp);
    }
    {
        float lo, hi;
        unpk(hAcc0, lo, hi); hB[w][0][2 * lane] = siluf(lo); hB[w][0][2 * lane + 1] = siluf(hi);
        unpk(hAcc1, lo, hi); hB[w][1][2 * lane] = siluf(lo); hB[w][1][2 * lane + 1] = siluf(hi);
        unpk(hAcc2, lo, hi); hB[w][2][2 * lane] = siluf(lo); hB[w][2][2 * lane + 1] = siluf(hi);
        unpk(hAcc3, lo, hi); hB[w][3][2 * lane] = siluf(lo); hB[w][3][2 * lane + 1] = siluf(hi);
    }
    __syncwarp();
    // fc2 (64->16) + LN16, half-warp split over k
    int c = lane & 15, half = lane >> 4;
#pragma unroll
    for (int t = 0; t < 4; t++) {
        float oc = 0.f;
#pragma unroll 8
        for (int k = 0; k < 32; k++) {
            int kk = half * 32 + k;
            oc = fmaf(hB[w][t][kk], sW2[kk * 16 + c], oc);
        }
        oc += __shfl_xor_sync(0xffffffffu, oc, 16);
        oc += sB2[c];
        float s2 = oc;
#pragma unroll
        for (int o = 8; o; o >>= 1) s2 += __shfl_xor_sync(0xffffffffu, s2, o);
        float mm = s2 * (1.f / 16.f);
        float dv = oc - mm;
        float vs = dv * dv;
#pragma unroll
        for (int o = 8; o; o >>= 1) vs += __shfl_xor_sync(0xffffffffu, vs, o);
        float rs = rsqrtf(vs * (1.f / 16.f) + 1e-5f);
        if (lane < 16) g_src[(aBase + t) * DDIM + lane] = fmaf(dv * rs, sSLnG[lane], sSLnB[lane]);
    }
}

// ---------------------------------------------------------------------------
// 2. Pairwise shell statistics (raw sums). R5 structure: 256 blocks,
//    warp-per-atom, centering fused (deterministic redundant mean).
// ---------------------------------------------------------------------------
#define PAIR_SMEM_FLOATS (2048 + 512 * 20 + 2 * NLUT + 8 * 95 * 9 + 256 + 16)
#define PAIR_SMEM (PAIR_SMEM_FLOATS * 4)

__global__ void __launch_bounds__(256, 2) pair_kernel(const float* __restrict__ pos) {
    extern __shared__ float psm[];
    float4* sP = (float4*)psm;                          // 512 float4
    float* sS = psm + 2048;                             // [512][20]
    float2* sLutB = (float2*)(psm + 2048 + 512 * 20);   // NLUT float2
    float* sRed = psm + 2048 + 512 * 20 + 2 * NLUT;     // [8][95][9]
    float* sPart = sRed + 8 * 95 * 9;                   // 256
    float* sMu = sPart + 256;                           // 16
    int tid = threadIdx.x;
    int g = blockIdx.x >> 4;
    int tile = blockIdx.x & 15;
    const float* pg = pos + g * NATOM * 3;
    for (int j = tid; j < NATOM; j += 256)
        sP[j] = make_float4(pg[j * 3 + 0], pg[j * 3 + 1], pg[j * 3 + 2], 0.f);
    const float* sgp = g_src + g * NATOM * DDIM;
    for (int idx = tid; idx < NATOM * 4; idx += 256) {
        int j = idx >> 2, c4 = idx & 3;
        float4 v = ((const float4*)(sgp + j * 16))[c4];
        *(float4*)(sS + j * 20 + c4 * 4) = v;
    }
    for (int i = tid; i < NLUT; i += 256) {
        float a = g_nodes[i], bb = g_nodes[i + 1];
        sLutB[i] = make_float2(a, (bb - a) * (1.f / 65536.f));
    }
    __syncthreads();
    // per-graph mean subtract (identical FP order per block -> deterministic)
    {
        int c = tid & 15, p = tid >> 4;
        float s = 0.f;
        for (int j = p; j < NATOM; j += 16) s += sS[j * 20 + c];
        sPart[tid] = s;
        __syncthreads();
        if (tid < 16) {
            float t = 0.f;
            for (int q = 0; q < 16; q++) t += sPart[q * 16 + tid];
            float mu = t * (1.f / (float)NATOM);
            sMu[tid] = mu;
            if (tile == 0) g_mu[g * 16 + tid] = mu;
        }
        __syncthreads();
        for (int j = p; j < NATOM; j += 16) sS[j * 20 + c] -= sMu[c];
        __syncthreads();
    }
    int w = tid >> 5, lane = tid & 31;
    float* red = sRed + w * (95 * 9);
    for (int t = 0; t < 4; t++) {
        int il = tile * 32 + w * 4 + t;
        float4 pi = sP[il];
        float px = pi.x, py = pi.y, pz = pi.z;
        unsigned long long accM[5][8];
        float accC[5], accR[5], accR2[5];
#pragma unroll
        for (int q = 0; q < 5; q++) {
            accC[q] = 0.f; accR[q] = 0.f; accR2[q] = 0.f;
#pragma unroll
            for (int p = 0; p < 8; p++) accM[q][p] = 0ull;
        }
#pragma unroll 2
        for (int jj = 0; jj < 16; jj++) {
            int j = jj * 32 + lane;
            float4 pj = sP[j];
            float dx = px - pj.x, dy = py - pj.y, dz = pz - pj.z;
            float d2 = fmaf(dx, dx, fmaf(dy, dy, fmaf(dz, dz, 1e-12f)));
            unsigned u = __float_as_uint(d2);
            int k = (int)(u >> 16) - 16256;
            k = min(max(k, 0), NLUT - 1);
            float fr = (float)(int)(u & 0xFFFFu);
            float2 L = sLutB[k];
            float ker = fmaf(L.y, fr, L.x);
            float d = sqrtf(d2);
            float m0 = (d2 >= 25.f && d2 < 100.f) ? 1.f : 0.f;
            float m1 = (d2 >= 100.f && d2 < 400.f) ? 1.f : 0.f;
            float m2 = (d2 >= 400.f && d2 < 1600.f) ? 1.f : 0.f;
            float m3 = (d2 >= 1600.f && d2 < 6400.f) ? 1.f : 0.f;
            float m4 = (d2 >= 6400.f) ? 1.f : 0.f;
            accC[0] += m0; accR[0] = fmaf(m0, d, accR[0]); accR2[0] = fmaf(m0, d2, accR2[0]);
            accC[1] += m1; accR[1] = fmaf(m1, d, accR[1]); accR2[1] = fmaf(m1, d2, accR2[1]);
            accC[2] += m2; accR[2] = fmaf(m2, d, accR[2]); accR2[2] = fmaf(m2, d2, accR2[2]);
            accC[3] += m3; accR[3] = fmaf(m3, d, accR[3]); accR2[3] = fmaf(m3, d2, accR2[3]);
            accC[4] += m4; accR[4] = fmaf(m4, d, accR[4]); accR2[4] = fmaf(m4, d2, accR2[4]);
            const ulonglong2* rp = (const ulonglong2*)(sS + j * 20);
            ulonglong2 u0 = rp[0], u1 = rp[1], u2 = rp[2], u3 = rp[3];
            unsigned long long W;
#define ACCQ(Q, MQ) { W = dup2(MQ * ker); \
            FMA2(accM[Q][0], W, u0.x); FMA2(accM[Q][1], W, u0.y); \
            FMA2(accM[Q][2], W, u1.x); FMA2(accM[Q][3], W, u1.y); \
            FMA2(accM[Q][4], W, u2.x); FMA2(accM[Q][5], W, u2.y); \
            FMA2(accM[Q][6], W, u3.x); FMA2(accM[Q][7], W, u3.y); }
            ACCQ(0, m0) ACCQ(1, m1) ACCQ(2, m2) ACCQ(3, m3) ACCQ(4, m4)
#undef ACCQ
        }
#define RED4(val, o) { float _v = (val); \
        _v += __shfl_xor_sync(0xffffffffu, _v, 1); \
        _v += __shfl_xor_sync(0xffffffffu, _v, 2); \
        if ((lane & 3) == 0) red[(o) * 9 + (lane >> 2)] = _v; }
#pragma unroll
        for (int q = 0; q < 5; q++) {
#pragma unroll
            for (int p = 0; p < 8; p++) {
                float lo_, hi_;
                unpk(accM[q][p], lo_, hi_);
                RED4(lo_, q * 19 + 2 * p);
                RED4(hi_, q * 19 + 2 * p + 1);
            }
            RED4(accC[q], q * 19 + 16);
            RED4(accR[q], q * 19 + 17);
            RED4(accR2[q], q * 19 + 18);
        }
#undef RED4
        __syncwarp();
        float* outp = g_shell + (g * NATOM + il) * SEIN;
        for (int o = lane; o < SEIN; o += 32) {
            float s = 0.f;
#pragma unroll
            for (int gg = 0; gg < 8; gg++) s += red[o * 9 + gg];
            outp[o] = s;
        }
        __syncwarp();
    }
}

// ---------------------------------------------------------------------------
// 3. Head: finalize raw shell sums, LNs + MLPs, per-block partial; last
//    block (atomic counter, self-resetting) reduces 256 partials -> out[16].
// ---------------------------------------------------------------------------
#define HEAD_SMEM_FLOATS (6080 + 64 + 1024 + 16 + 10176 + 64 + 64 + 16 + 96 + 96 + 160 + 160 + 1280 + 512 + 16)
#define HEAD_SMEM (HEAD_SMEM_FLOATS * 4)

__device__ __forceinline__ float fin_shell(float v, int o, float i0, float i1, float i2,
                                           float i3, float i4) {
    int q = o / 19;
    int k = o - q * 19;
    float dv = (q == 0) ? i0 : (q == 1) ? i1 : (q == 2) ? i2 : (q == 3) ? i3 : i4;
    if (k == 16) return v;
    if (k == 18) return sqrtf(fmaf(v, dv, 1e-12f));
    return v * dv;
}

__global__ void __launch_bounds__(256) head_kernel(
    const float* __restrict__ seLnG_, const float* __restrict__ seLnB_,
    const float* __restrict__ seW1_, const float* __restrict__ seB1_,
    const float* __restrict__ seW2_, const float* __restrict__ seB2_,
    const float* __restrict__ ehLnG_, const float* __restrict__ ehLnB_,
    const float* __restrict__ ehW1_, const float* __restrict__ ehB1_,
    const float* __restrict__ ehW2_, const float* __restrict__ ehB2_,
    const float* __restrict__ far_gate, const float* __restrict__ energy_scale,
    float* __restrict__ out) {
    extern __shared__ float sm[];
    __shared__ unsigned sDone;
    float* seW1 = sm;
    float* seB1 = seW1 + 6080;
    float* seW2 = seB1 + 64;
    float* seB2 = seW2 + 1024;
    float* ehW1 = seB2 + 16;
    float* ehB1 = ehW1 + 10176;
    float* ehW2 = ehB1 + 64;
    float* ehB2s = ehW2 + 64;
    float* seLnG = ehB2s + 16;
    float* seLnB = seLnG + 96;
    float* ehLnG = seLnB + 96;
    float* ehLnB = ehLnG + 160;
    float* zALL = ehLnB + 160;
    float* hALL = zALL + 1280;
    float* sWsum = hALL + 512;
    int tid = threadIdx.x;
    for (int i = tid; i < 6080; i += 256) seW1[i] = seW1_[i];
    for (int i = tid; i < 1024; i += 256) seW2[i] = seW2_[i];
    for (int i = tid; i < 10176; i += 256) ehW1[i] = ehW1_[i];
    if (tid < 64) { seB1[tid] = seB1_[tid]; ehB1[tid] = ehB1_[tid]; ehW2[tid] = ehW2_[tid]; }
    if (tid < 16) seB2[tid] = seB2_[tid];
    if (tid == 0) ehB2s[0] = ehB2_[0];
    if (tid < 95) { seLnG[tid] = seLnG_[tid]; seLnB[tid] = seLnB_[tid]; }
    if (tid < 159) { ehLnG[tid] = ehLnG_[tid]; ehLnB[tid] = ehLnB_[tid]; }
    __syncthreads();
    int w = tid >> 5, lane = tid & 31;
    float* z = zALL + w * 160;
    float* h = hALL + w * 64;
    float scale = tanhf(*far_gate) * expf(*energy_scale);
    float wsum = 0.f;
    for (int t = 0; t < 4; t++) {
        int a = blockIdx.x * 32 + w * 4 + t;
        int g = a >> 9;
        const float* shp = g_shell + a * SEIN;
        float v0 = shp[lane];
        float v1 = shp[lane + 32];
        float v2 = (lane < 31) ? shp[lane + 64] : 0.f;
        float C0 = __shfl_sync(0xffffffffu, v0, 16);
        float C1 = __shfl_sync(0xffffffffu, v1, 3);
        float C2 = __shfl_sync(0xffffffffu, v1, 22);
        float C3 = __shfl_sync(0xffffffffu, v2, 9);
        float C4 = __shfl_sync(0xffffffffu, v2, 28);
        float i0 = 1.f / fmaxf(C0, 1.f), i1 = 1.f / fmaxf(C1, 1.f);
        float i2 = 1.f / fmaxf(C2, 1.f), i3 = 1.f / fmaxf(C3, 1.f);
        float i4 = 1.f / fmaxf(C4, 1.f);
        v0 = fin_shell(v0, lane, i0, i1, i2, i3, i4);
        v1 = fin_shell(v1, lane + 32, i0, i1, i2, i3, i4);
        v2 = (lane < 31) ? fin_shell(v2, lane + 64, i0, i1, i2, i3, i4) : 0.f;
        float s = wred(v0 + v1 + v2);
        float m = s * (1.f / 95.f);
        float e0 = v0 - m, e1 = v1 - m, e2 = (lane < 31) ? (v2 - m) : 0.f;
        float ss = wred(e0 * e0 + e1 * e1 + e2 * e2);
        float rstd = rsqrtf(ss * (1.f / 95.f) + 1e-5f);
        z[lane] = fmaf(e0 * rstd, seLnG[lane], seLnB[lane]);
        z[lane + 32] = fmaf(e1 * rstd, seLnG[lane + 32], seLnB[lane + 32]);
        if (lane < 31) z[lane + 64] = fmaf(e2 * rstd, seLnG[lane + 64], seLnB[lane + 64]);
        __syncwarp();
        float h0 = seB1[lane], h1 = seB1[lane + 32];
        for (int k = 0; k < 95; k++) {
            float zv = z[k];
            h0 = fmaf(zv, seW1[k * 64 + lane], h0);
            h1 = fmaf(zv, seW1[k * 64 + lane + 32], h1);
        }
        h[lane] = siluf(h0);
        h[lane + 32] = siluf(h1);
        __syncwarp();
        float srcc = 0.f, embc = 0.f;
        if (lane < 16) {
            embc = seB2[lane];
            for (int k = 0; k < 64; k++) embc = fmaf(h[k], seW2[k * 16 + lane], embc);
            srcc = g_src[a * DDIM + lane] - g_mu[g * 16 + lane];
        }
        __syncwarp();
        if (lane < 16) {
            z[lane] = srcc;
            z[16 + lane] = embc;
            z[32 + lane] = srcc * embc;
            z[48 + lane] = srcc - embc;
        }
        z[64 + lane] = v0;
        z[96 + lane] = v1;
        if (lane < 31) z[128 + lane] = v2;
        __syncwarp();
        float a0 = z[lane], a1 = z[lane + 32], a2 = z[lane + 64], a3 = z[lane + 96];
        float a4 = (lane < 31) ? z[lane + 128] : 0.f;
        float s2 = wred(a0 + a1 + a2 + a3 + a4);
        float m2 = s2 * (1.f / 159.f);
        float q0 = a0 - m2, q1 = a1 - m2, q2 = a2 - m2, q3 = a3 - m2;
        float q4 = (lane < 31) ? (a4 - m2) : 0.f;
        float ss2 = wred(q0 * q0 + q1 * q1 + q2 * q2 + q3 * q3 + q4 * q4);
        float rstd2 = rsqrtf(ss2 * (1.f / 159.f) + 1e-5f);
        z[lane] = fmaf(q0 * rstd2, ehLnG[lane], ehLnB[lane]);
        z[lane + 32] = fmaf(q1 * rstd2, ehLnG[lane + 32], ehLnB[lane + 32]);
        z[lane + 64] = fmaf(q2 * rstd2, ehLnG[lane + 64], ehLnB[lane + 64]);
        z[lane + 96] = fmaf(q3 * rstd2, ehLnG[lane + 96], ehLnB[lane + 96]);
        if (lane < 31) z[lane + 128] = fmaf(q4 * rstd2, ehLnG[lane + 128], ehLnB[lane + 128]);
        __syncwarp();
        float g0 = ehB1[lane], g1 = ehB1[lane + 32];
        for (int k = 0; k < 159; k++) {
            float zv = z[k];
            g0 = fmaf(zv, ehW1[k * 64 + lane], g0);
            g1 = fmaf(zv, ehW1[k * 64 + lane + 32], g1);
        }
        g0 = siluf(g0);
        g1 = siluf(g1);
        float p = wred(g0 * ehW2[lane] + g1 * ehW2[lane + 32]);
        if (lane == 0) wsum += (p + ehB2s[0]) * scale;
        __syncwarp();
    }
    if (lane == 0) sWsum[w] = wsum;
    __syncthreads();
    if (tid == 0) {
        float ssum = 0.f;
#pragma unroll
        for (int q = 0; q < 8; q++) ssum += sWsum[q];
        g_part[blockIdx.x] = ssum;
        __threadfence();
        unsigned o = atomicAdd(&g_ctr, 1u);
        sDone = (o == 255u) ? 1u : 0u;
    }
    __syncthreads();
    if (sDone) {
        float v = g_part[tid];
        v += __shfl_xor_sync(0xffffffffu, v, 1);
        v += __shfl_xor_sync(0xffffffffu, v, 2);
        v += __shfl_xor_sync(0xffffffffu, v, 4);
        v += __shfl_xor_sync(0xffffffffu, v, 8);
        if ((tid & 15) == 0) out[tid >> 4] = v;
        if (tid == 0) g_ctr = 0u;
    }
}

extern "C" void kernel_launch(void* const* d_in, const int* in_sizes, int n_in,
                              void* d_out, int out_size) {
    const float* x = (const float*)d_in[0];
    const float* pos = (const float*)d_in[1];
    const float* in_ln_g = (const float*)d_in[4];
    const float* in_ln_b = (const float*)d_in[5];
    const float* src_w1 = (const float*)d_in[6];
    const float* src_b1 = (const float*)d_in[7];
    const float* src_w2 = (const float*)d_in[8];
    const float* src_b2 = (const float*)d_in[9];
    const float* src_ln_g = (const float*)d_in[10];
    const float* src_ln_b = (const float*)d_in[11];
    const float* se_ln_g = (const float*)d_in[12];
    const float* se_ln_b = (const float*)d_in[13];
    const float* se_w1 = (const float*)d_in[14];
    const float* se_b1 = (const float*)d_in[15];
    const float* se_w2 = (const float*)d_in[16];
    const float* se_b2 = (const float*)d_in[17];
    const float* eh_ln_g = (const float*)d_in[18];
    const float* eh_ln_b = (const float*)d_in[19];
    const float* eh_w1 = (const float*)d_in[20];
    const float* eh_b1 = (const float*)d_in[21];
    const float* eh_w2 = (const float*)d_in[22];
    const float* eh_b2 = (const float*)d_in[23];
    const float* k_screen = (const float*)d_in[24];
    const float* kg_w1 = (const float*)d_in[25];
    const float* kg_b1 = (const float*)d_in[26];
    const float* kg_w2 = (const float*)d_in[27];
    const float* kg_b2 = (const float*)d_in[28];
    const float* far_gate = (const float*)d_in[29];
    const float* energy_scale = (const float*)d_in[30];
    float* out = (float*)d_out;

    cudaFuncSetAttribute(pair_kernel, cudaFuncAttributeMaxDynamicSharedMemorySize, PAIR_SMEM);
    cudaFuncSetAttribute(head_kernel, cudaFuncAttributeMaxDynamicSharedMemorySize, HEAD_SMEM);

    src_lut_kernel<<<256 + (NLUT + 1 + 255) / 256, 256>>>(
        x, src_w1, src_b1, src_w2, src_b2, in_ln_g, in_ln_b, src_ln_g, src_ln_b,
        k_screen, kg_w1, kg_b1, kg_w2, kg_b2);
    pair_kernel<<<NGRAPH * 16, 256, PAIR_SMEM>>>(pos);
    head_kernel<<<MATOMS / 32, 256, HEAD_SMEM>>>(se_ln_g, se_ln_b, se_w1, se_b1, se_w2, se_b2,
                                                 eh_ln_g, eh_ln_b, eh_w1, eh_b1, eh_w2, eh_b2,
                                                 far_gate, energy_scale, out);
}